// round 1
// baseline (speedup 1.0000x reference)
#include <cuda_runtime.h>
#include <math.h>

#define NN 10000
#define KK 16
#define EE (NN*KK)
#define HH 100
#define NB 10

// ---------------- scratch (static device globals; no allocation) ----------------
__device__ float g_basis[EE*NB];          // 6.4 MB
__device__ float g_u[EE*3];               // 1.9 MB
__device__ float g_h1[EE*HH];             // 64 MB
__device__ float g_h2[EE*HH];             // 64 MB
__device__ float g_W[(size_t)EE*832];     // 532 MB (max Wtot)
__device__ float g_f0a[NN*32];
__device__ float g_f0b[NN*32];
__device__ float g_f1a[NN*24];
__device__ float g_f1b[NN*24];

// ---------------- prep: per-edge r, unit vector, cosine basis ----------------
__global__ void prep_kernel(const float* __restrict__ radii) {
    int e = blockIdx.x*blockDim.x + threadIdx.x;
    if (e >= EE) return;
    float x = radii[e*3+0], y = radii[e*3+1], z = radii[e*3+2];
    float r = sqrtf(x*x + y*y + z*z);
    float inv = 1.0f / (r + 1e-8f);
    g_u[e*3+0] = x*inv; g_u[e*3+1] = y*inv; g_u[e*3+2] = z*inv;
    float rs = r * 1.8f;                 // r / step, step = 5/9
    #pragma unroll
    for (int b = 0; b < NB; b++) {
        float d = rs - (float)b;
        float v = 0.f;
        if (fabsf(d) < 1.0f) {
            float c = cospif(0.5f * d); // cos(pi/2 * d)
            v = c * c;
        }
        g_basis[e*NB + b] = v;
    }
}

// ---------------- fp32 tiled GEMM: C[M,N] = act(A[M,K] @ B[K,N] + bias) ----------------
// BM=BN=64, BK<=50, 256 threads, 4x4 micro-tile per thread.
template<bool RELU>
__global__ void gemm_kernel(const float* __restrict__ A, const float* __restrict__ B,
                            const float* __restrict__ bias, float* __restrict__ C,
                            int M, int N, int K) {
    __shared__ __align__(16) float As[64*50];
    __shared__ __align__(16) float Bs[50*64];
    int tid = threadIdx.x;
    int m0 = blockIdx.y * 64, n0 = blockIdx.x * 64;
    int tx = tid & 15, ty = tid >> 4;
    int row = ty*4, col = tx*4;
    float acc[4][4] = {};

    for (int kc = 0; kc < K; kc += 50) {
        int kl = min(50, K - kc);
        // A tile: rows m0..m0+63, cols kc..kc+kl-1 ; layout As[m*kl + k]
        for (int i = tid; i < 64*kl; i += 256) {
            int m = i / kl, k = i - m*kl;
            As[i] = A[(size_t)(m0+m)*K + kc + k];
        }
        // B tile: Bs[k*64 + n], zero-pad beyond N
        for (int i = tid; i < kl*64; i += 256) {
            int k = i >> 6, n = i & 63;
            Bs[i] = (n0 + n < N) ? B[(size_t)(kc+k)*N + n0 + n] : 0.f;
        }
        __syncthreads();
        #pragma unroll 2
        for (int k = 0; k < kl; k++) {
            float4 b4 = *reinterpret_cast<const float4*>(&Bs[(k<<6) + col]);
            float a0 = As[(row+0)*kl + k];
            float a1 = As[(row+1)*kl + k];
            float a2 = As[(row+2)*kl + k];
            float a3 = As[(row+3)*kl + k];
            acc[0][0] += a0*b4.x; acc[0][1] += a0*b4.y; acc[0][2] += a0*b4.z; acc[0][3] += a0*b4.w;
            acc[1][0] += a1*b4.x; acc[1][1] += a1*b4.y; acc[1][2] += a1*b4.z; acc[1][3] += a1*b4.w;
            acc[2][0] += a2*b4.x; acc[2][1] += a2*b4.y; acc[2][2] += a2*b4.z; acc[2][3] += a2*b4.w;
            acc[3][0] += a3*b4.x; acc[3][1] += a3*b4.y; acc[3][2] += a3*b4.z; acc[3][3] += a3*b4.w;
        }
        __syncthreads();
    }
    #pragma unroll
    for (int i = 0; i < 4; i++) {
        size_t cr = (size_t)(m0+row+i)*N;
        #pragma unroll
        for (int j = 0; j < 4; j++) {
            int cn = n0 + col + j;
            if (cn < N) {
                float v = acc[i][j];
                if (bias) v += bias[cn];
                if (RELU) v = fmaxf(v, 0.f);
                C[cr + cn] = v;
            }
        }
    }
}

// ---------------- tensor product + mean-over-K + gated nonlinearity ----------------
// One block (64 threads) per node. Each thread owns one output (scalar or vector comp).
template<int LAYER>
__global__ void tp_kernel(const int* __restrict__ nbr, const int* __restrict__ charges) {
    constexpr int M0I = (LAYER==1) ? 1 : 16;
    constexpr int M1I = (LAYER==1) ? 0 : 8;
    constexpr int M0O = (LAYER==3) ? 32 : 16;
    constexpr int NG  = (LAYER==3) ? 0 : 8;
    constexpr int M1O = (LAYER==3) ? 0 : 8;
    constexpr int M0T = M0O + NG;
    constexpr int OFF1 = M0T*M0I;
    constexpr int OFF2 = OFF1 + M0T*M1I;
    constexpr int OFF3 = OFF2 + M1O*M0I;
    constexpr int OFF4 = OFF3 + M1O*M1I;
    constexpr int WTOT = OFF4 + M1O*M1I;

    const float* __restrict__ f0_in = (LAYER==2) ? g_f0a : g_f0b;
    const float* __restrict__ f1_in = (LAYER==2) ? g_f1a : g_f1b;
    float* f0_out = (LAYER==2) ? g_f0b : g_f0a;
    float* f1_out = (LAYER==2) ? g_f1b : g_f1a;

    int n = blockIdx.x;
    int tid = threadIdx.x;

    __shared__ float g0s[16], us[3], g1s[24], ps[8], gates[8];

    float acc = 0.f;

    for (int k = 0; k < KK; k++) {
        int e = n*KK + k;
        int idx = nbr[e];
        if (LAYER == 1) {
            if (tid == 0) g0s[0] = 0.5f * ((float)charges[idx] / 94.0f - 0.5f);
        } else {
            if (tid < M0I) g0s[tid] = 0.5f * f0_in[idx*M0I + tid];
        }
        if (tid >= 32 && tid < 35) us[tid-32] = g_u[e*3 + (tid-32)];
        if (M1I > 0) {
            if (tid >= 36 && tid < 36 + M1I*3) g1s[tid-36] = 0.5f * f1_in[idx*(M1I*3) + (tid-36)];
        }
        __syncthreads();
        if (M1I > 0) {
            if (tid < M1I) ps[tid] = g1s[tid*3]*us[0] + g1s[tid*3+1]*us[1] + g1s[tid*3+2]*us[2];
        }
        __syncthreads();
        const float* __restrict__ We = g_W + (size_t)e * WTOT;
        if (tid < M0T) {
            float s = 0.f;
            #pragma unroll
            for (int i = 0; i < M0I; i++) s += We[tid*M0I + i] * g0s[i];
            if (M1I > 0) {
                #pragma unroll
                for (int i = 0; i < M1I; i++) s += We[OFF1 + tid*M1I + i] * ps[i];
            }
            acc += s;
        } else if (M1O > 0 && tid < M0T + 3*M1O) {
            int q = tid - M0T, o = q/3, c = q - o*3;
            float dot = 0.f;
            #pragma unroll
            for (int i = 0; i < M0I; i++) dot += We[OFF2 + o*M0I + i] * g0s[i];
            float vv = dot * us[c];
            if (M1I > 0) {
                int c1 = (c+1)%3, c2 = (c+2)%3;
                #pragma unroll
                for (int i = 0; i < M1I; i++) vv += We[OFF3 + o*M1I + i] * g1s[i*3 + c];
                #pragma unroll
                for (int i = 0; i < M1I; i++)
                    vv += We[OFF4 + o*M1I + i] * (g1s[i*3+c1]*us[c2] - g1s[i*3+c2]*us[c1]);
            }
            acc += vv;
        }
        __syncthreads();
    }

    float m = acc * (1.0f/16.0f);
    if (tid < M0O) {
        f0_out[n*M0O + tid] = fmaxf(m, 0.f);
    } else if (tid < M0T) {
        gates[tid - M0O] = 1.0f / (1.0f + expf(-m));
    }
    __syncthreads();
    if (M1O > 0 && tid >= M0T && tid < M0T + 3*M1O) {
        int q = tid - M0T, o = q/3, c = q - o*3;
        f1_out[(n*M1O + o)*3 + c] = m * gates[o];
    }
}

// ---------------- final reduce: out[j] = mean_n f0[n, j] ----------------
__global__ void reduce_kernel(float* __restrict__ out) {
    __shared__ float red[256];
    int j = blockIdx.x;           // 0..31
    float s = 0.f;
    for (int n = threadIdx.x; n < NN; n += 256) s += g_f0a[n*32 + j];
    red[threadIdx.x] = s;
    __syncthreads();
    for (int w = 128; w > 0; w >>= 1) {
        if (threadIdx.x < w) red[threadIdx.x] += red[threadIdx.x + w];
        __syncthreads();
    }
    if (threadIdx.x == 0) out[j] = red[0] * (1.0f/NN);
}

// ---------------- host ----------------
extern "C" void kernel_launch(void* const* d_in, const int* in_sizes, int n_in,
                              void* d_out, int out_size) {
    const float* radii   = (const float*)d_in[0];
    const int*   nbr     = (const int*)d_in[1];
    const int*   charges = (const int*)d_in[2];

    void* p;
    cudaGetSymbolAddress(&p, g_basis); float* basis = (float*)p;
    cudaGetSymbolAddress(&p, g_h1);    float* h1    = (float*)p;
    cudaGetSymbolAddress(&p, g_h2);    float* h2    = (float*)p;
    cudaGetSymbolAddress(&p, g_W);     float* W     = (float*)p;

    prep_kernel<<<(EE+255)/256, 256>>>(radii);

    const int wtot[3] = {32, 832, 768};
    for (int l = 0; l < 3; l++) {
        const float* w1 = (const float*)d_in[3 + 5*l + 0];
        const float* b1 = (const float*)d_in[3 + 5*l + 1];
        const float* w2 = (const float*)d_in[3 + 5*l + 2];
        const float* b2 = (const float*)d_in[3 + 5*l + 3];
        const float* w3 = (const float*)d_in[3 + 5*l + 4];

        dim3 gridH(2, EE/64);                      // N=100 -> 2 col tiles
        gemm_kernel<true ><<<gridH, 256>>>(basis, w1, b1, h1, EE, HH, NB);
        gemm_kernel<true ><<<gridH, 256>>>(h1,    w2, b2, h2, EE, HH, HH);
        dim3 gridW((wtot[l]+63)/64, EE/64);
        gemm_kernel<false><<<gridW, 256>>>(h2,    w3, nullptr, W, EE, wtot[l], HH);

        if      (l == 0) tp_kernel<1><<<NN, 64>>>(nbr, charges);
        else if (l == 1) tp_kernel<2><<<NN, 64>>>(nbr, charges);
        else             tp_kernel<3><<<NN, 64>>>(nbr, charges);
    }
    reduce_kernel<<<32, 256>>>((float*)d_out);
}

// round 2
// speedup vs baseline: 1.1459x; 1.1459x over previous
#include <cuda_runtime.h>
#include <math.h>
#include <stdint.h>

#define NN 10000
#define KK 16
#define EE (NN*KK)
#define HH 100
#define NB 10

// ---------------- scratch ----------------
__device__ float g_basis[EE*NB];
__device__ float g_u[EE*3];
__device__ float g_h1[EE*HH];
__device__ float g_h2[EE*HH];
__device__ float g_W[(size_t)EE*832];
__device__ float g_f0a[NN*32];
__device__ float g_f0b[NN*32];
__device__ float g_f1a[NN*24];
__device__ float g_f1b[NN*24];

// ---------------- prep ----------------
__global__ void prep_kernel(const float* __restrict__ radii) {
    int e = blockIdx.x*blockDim.x + threadIdx.x;
    if (e >= EE) return;
    float x = radii[e*3+0], y = radii[e*3+1], z = radii[e*3+2];
    float r = sqrtf(x*x + y*y + z*z);
    float inv = 1.0f / (r + 1e-8f);
    g_u[e*3+0] = x*inv; g_u[e*3+1] = y*inv; g_u[e*3+2] = z*inv;
    float rs = r * 1.8f;
    #pragma unroll
    for (int b = 0; b < NB; b++) {
        float d = rs - (float)b;
        float v = 0.f;
        if (fabsf(d) < 1.0f) {
            float c = cospif(0.5f * d);
            v = c * c;
        }
        g_basis[e*NB + b] = v;
    }
}

// ---------------- tf32 helpers ----------------
__device__ __forceinline__ float f2tf32f(float v) {
    uint32_t r;
    asm("cvt.rna.tf32.f32 %0, %1;" : "=r"(r) : "f"(v));
    return __uint_as_float(r);
}

__device__ __forceinline__ void mma_tf32(float* c, const uint32_t* a, const uint32_t* b) {
    asm volatile("mma.sync.aligned.m16n8k8.row.col.f32.tf32.tf32.f32 "
        "{%0,%1,%2,%3}, {%4,%5,%6,%7}, {%8,%9}, {%0,%1,%2,%3};"
        : "+f"(c[0]), "+f"(c[1]), "+f"(c[2]), "+f"(c[3])
        : "r"(a[0]), "r"(a[1]), "r"(a[2]), "r"(a[3]), "r"(b[0]), "r"(b[1]));
}

// ---------------- tf32 tensor-core GEMM ----------------
// C[M,N] = act(A[M,K] @ B[K,N] + bias). BM=128, BN=64, BK=32.
// 256 threads = 8 warps in 4(m) x 2(n); warp tile 32x32 = 2x4 m16n8k8 frags.
template<bool RELU>
__global__ void gemm_tf32(const float* __restrict__ A, const float* __restrict__ B,
                          const float* __restrict__ bias, float* __restrict__ C,
                          int M, int N, int K) {
    __shared__ float As[128*33];   // [m][k], stride 33
    __shared__ float Bs[32*65];    // [k][n], stride 65

    const int tid = threadIdx.x;
    const int lane = tid & 31, wid = tid >> 5;
    const int wm = (wid & 3) * 32;       // warp m offset
    const int wn = (wid >> 2) * 32;      // warp n offset
    const int m0 = blockIdx.y * 128, n0 = blockIdx.x * 64;
    const int gr = lane >> 2, tg = lane & 3;

    float acc[2][4][4];
    #pragma unroll
    for (int t = 0; t < 2; t++)
        #pragma unroll
        for (int j = 0; j < 4; j++)
            #pragma unroll
            for (int q = 0; q < 4; q++) acc[t][j][q] = 0.f;

    for (int kc = 0; kc < K; kc += 32) {
        // fill A tile (cvt to tf32 at store time)
        #pragma unroll 2
        for (int i = tid; i < 128*32; i += 256) {
            int m = i >> 5, k = i & 31, gk = kc + k;
            float v = (gk < K) ? A[(size_t)(m0+m)*K + gk] : 0.f;
            As[m*33 + k] = f2tf32f(v);
        }
        #pragma unroll 2
        for (int i = tid; i < 32*64; i += 256) {
            int k = i >> 6, n = i & 63, gk = kc + k;
            float v = (gk < K && n0 + n < N) ? B[(size_t)gk*N + n0 + n] : 0.f;
            Bs[k*65 + n] = f2tf32f(v);
        }
        __syncthreads();

        #pragma unroll
        for (int k8 = 0; k8 < 4; k8++) {
            int k0 = k8 * 8;
            uint32_t a[2][4], b[4][2];
            #pragma unroll
            for (int t = 0; t < 2; t++) {
                int row = wm + t*16 + gr;
                a[t][0] = __float_as_uint(As[row*33     + k0 + tg]);
                a[t][1] = __float_as_uint(As[(row+8)*33 + k0 + tg]);
                a[t][2] = __float_as_uint(As[row*33     + k0 + 4 + tg]);
                a[t][3] = __float_as_uint(As[(row+8)*33 + k0 + 4 + tg]);
            }
            #pragma unroll
            for (int j = 0; j < 4; j++) {
                int col = wn + j*8 + gr;
                b[j][0] = __float_as_uint(Bs[(k0 + tg)*65     + col]);
                b[j][1] = __float_as_uint(Bs[(k0 + 4 + tg)*65 + col]);
            }
            #pragma unroll
            for (int t = 0; t < 2; t++)
                #pragma unroll
                for (int j = 0; j < 4; j++)
                    mma_tf32(acc[t][j], a[t], b[j]);
        }
        __syncthreads();
    }

    // epilogue
    #pragma unroll
    for (int t = 0; t < 2; t++) {
        #pragma unroll
        for (int j = 0; j < 4; j++) {
            int row = m0 + wm + t*16 + gr;
            int col = n0 + wn + j*8 + tg*2;
            #pragma unroll
            for (int h = 0; h < 2; h++) {     // c0/c1 then c2/c3 (row+8)
                int r = row + h*8;
                #pragma unroll
                for (int q = 0; q < 2; q++) {
                    int cn = col + q;
                    if (cn < N) {
                        float v = acc[t][j][h*2 + q];
                        if (bias) v += bias[cn];
                        if (RELU) v = fmaxf(v, 0.f);
                        C[(size_t)r*N + cn] = v;
                    }
                }
            }
        }
    }
}

// ---------------- tensor product + mean-over-K + gated nonlinearity ----------------
template<int LAYER>
__global__ void tp_kernel(const int* __restrict__ nbr, const int* __restrict__ charges) {
    constexpr int M0I = (LAYER==1) ? 1 : 16;
    constexpr int M1I = (LAYER==1) ? 0 : 8;
    constexpr int M0O = (LAYER==3) ? 32 : 16;
    constexpr int NG  = (LAYER==3) ? 0 : 8;
    constexpr int M1O = (LAYER==3) ? 0 : 8;
    constexpr int M0T = M0O + NG;
    constexpr int OFF1 = M0T*M0I;
    constexpr int OFF2 = OFF1 + M0T*M1I;
    constexpr int OFF3 = OFF2 + M1O*M0I;
    constexpr int OFF4 = OFF3 + M1O*M1I;
    constexpr int WTOT = OFF4 + M1O*M1I;

    const float* __restrict__ f0_in = (LAYER==2) ? g_f0a : g_f0b;
    const float* __restrict__ f1_in = (LAYER==2) ? g_f1a : g_f1b;
    float* f0_out = (LAYER==2) ? g_f0b : g_f0a;
    float* f1_out = (LAYER==2) ? g_f1b : g_f1a;

    int n = blockIdx.x;
    int tid = threadIdx.x;

    __shared__ float g0s[16], us[3], g1s[24], ps[8], gates[8];

    float acc = 0.f;

    for (int k = 0; k < KK; k++) {
        int e = n*KK + k;
        int idx = nbr[e];
        if (LAYER == 1) {
            if (tid == 0) g0s[0] = 0.5f * ((float)charges[idx] / 94.0f - 0.5f);
        } else {
            if (tid < M0I) g0s[tid] = 0.5f * f0_in[idx*M0I + tid];
        }
        if (tid >= 32 && tid < 35) us[tid-32] = g_u[e*3 + (tid-32)];
        if (M1I > 0) {
            if (tid >= 36 && tid < 36 + M1I*3) g1s[tid-36] = 0.5f * f1_in[idx*(M1I*3) + (tid-36)];
        }
        __syncthreads();
        if (M1I > 0) {
            if (tid < M1I) ps[tid] = g1s[tid*3]*us[0] + g1s[tid*3+1]*us[1] + g1s[tid*3+2]*us[2];
        }
        __syncthreads();
        const float* __restrict__ We = g_W + (size_t)e * WTOT;
        if (tid < M0T) {
            float s = 0.f;
            #pragma unroll
            for (int i = 0; i < M0I; i++) s += We[tid*M0I + i] * g0s[i];
            if (M1I > 0) {
                #pragma unroll
                for (int i = 0; i < M1I; i++) s += We[OFF1 + tid*M1I + i] * ps[i];
            }
            acc += s;
        } else if (M1O > 0 && tid < M0T + 3*M1O) {
            int q = tid - M0T, o = q/3, c = q - o*3;
            float dot = 0.f;
            #pragma unroll
            for (int i = 0; i < M0I; i++) dot += We[OFF2 + o*M0I + i] * g0s[i];
            float vv = dot * us[c];
            if (M1I > 0) {
                int c1 = (c+1)%3, c2 = (c+2)%3;
                #pragma unroll
                for (int i = 0; i < M1I; i++) vv += We[OFF3 + o*M1I + i] * g1s[i*3 + c];
                #pragma unroll
                for (int i = 0; i < M1I; i++)
                    vv += We[OFF4 + o*M1I + i] * (g1s[i*3+c1]*us[c2] - g1s[i*3+c2]*us[c1]);
            }
            acc += vv;
        }
        __syncthreads();
    }

    float m = acc * (1.0f/16.0f);
    if (tid < M0O) {
        f0_out[n*M0O + tid] = fmaxf(m, 0.f);
    } else if (tid < M0T) {
        gates[tid - M0O] = 1.0f / (1.0f + expf(-m));
    }
    __syncthreads();
    if (M1O > 0 && tid >= M0T && tid < M0T + 3*M1O) {
        int q = tid - M0T, o = q/3, c = q - o*3;
        f1_out[(n*M1O + o)*3 + c] = m * gates[o];
    }
}

// ---------------- final reduce ----------------
__global__ void reduce_kernel(float* __restrict__ out) {
    __shared__ float red[256];
    int j = blockIdx.x;
    float s = 0.f;
    for (int n = threadIdx.x; n < NN; n += 256) s += g_f0a[n*32 + j];
    red[threadIdx.x] = s;
    __syncthreads();
    for (int w = 128; w > 0; w >>= 1) {
        if (threadIdx.x < w) red[threadIdx.x] += red[threadIdx.x + w];
        __syncthreads();
    }
    if (threadIdx.x == 0) out[j] = red[0] * (1.0f/NN);
}

// ---------------- host ----------------
extern "C" void kernel_launch(void* const* d_in, const int* in_sizes, int n_in,
                              void* d_out, int out_size) {
    const float* radii   = (const float*)d_in[0];
    const int*   nbr     = (const int*)d_in[1];
    const int*   charges = (const int*)d_in[2];

    void* p;
    cudaGetSymbolAddress(&p, g_basis); float* basis = (float*)p;
    cudaGetSymbolAddress(&p, g_h1);    float* h1    = (float*)p;
    cudaGetSymbolAddress(&p, g_h2);    float* h2    = (float*)p;
    cudaGetSymbolAddress(&p, g_W);     float* W     = (float*)p;

    prep_kernel<<<(EE+255)/256, 256>>>(radii);

    const int wtot[3] = {32, 832, 768};
    for (int l = 0; l < 3; l++) {
        const float* w1 = (const float*)d_in[3 + 5*l + 0];
        const float* b1 = (const float*)d_in[3 + 5*l + 1];
        const float* w2 = (const float*)d_in[3 + 5*l + 2];
        const float* b2 = (const float*)d_in[3 + 5*l + 3];
        const float* w3 = (const float*)d_in[3 + 5*l + 4];

        dim3 gridH((HH + 63)/64, EE/128);
        gemm_tf32<true ><<<gridH, 256>>>(basis, w1, b1, h1, EE, HH, NB);
        gemm_tf32<true ><<<gridH, 256>>>(h1,    w2, b2, h2, EE, HH, HH);
        dim3 gridW((wtot[l] + 63)/64, EE/128);
        gemm_tf32<false><<<gridW, 256>>>(h2,    w3, nullptr, W, EE, wtot[l], HH);

        if      (l == 0) tp_kernel<1><<<NN, 64>>>(nbr, charges);
        else if (l == 1) tp_kernel<2><<<NN, 64>>>(nbr, charges);
        else             tp_kernel<3><<<NN, 64>>>(nbr, charges);
    }
    reduce_kernel<<<32, 256>>>((float*)d_out);
}

// round 4
// speedup vs baseline: 2.1348x; 1.8630x over previous
#include <cuda_runtime.h>
#include <math.h>
#include <stdint.h>

#define NN 10000
#define KK 16
#define EE (NN*KK)
#define HH 100
#define NB 10
#define NBP 16   // padded basis width (16B-aligned rows for cp.async)

// ---------------- scratch ----------------
__device__ float g_basis[EE*NBP];
__device__ float g_u[EE*3];
__device__ float g_h1[EE*HH];
__device__ float g_h2[EE*HH];
__device__ float g_W[(size_t)EE*832];
__device__ float g_f0a[NN*32];
__device__ float g_f0b[NN*32];
__device__ float g_f1a[NN*24];
__device__ float g_f1b[NN*24];
__device__ float g_w1t[NBP*HH];
__device__ float g_w2t[HH*HH];
__device__ float g_w3t[HH*832];

// ---------------- helpers ----------------
__device__ __forceinline__ float f2tf32f(float v) {
    uint32_t r;
    asm("cvt.rna.tf32.f32 %0, %1;" : "=r"(r) : "f"(v));
    return __uint_as_float(r);
}

__device__ __forceinline__ void mma_tf32(float* c, const uint32_t* a, const uint32_t* b) {
    asm volatile("mma.sync.aligned.m16n8k8.row.col.f32.tf32.tf32.f32 "
        "{%0,%1,%2,%3}, {%4,%5,%6,%7}, {%8,%9}, {%0,%1,%2,%3};"
        : "+f"(c[0]), "+f"(c[1]), "+f"(c[2]), "+f"(c[3])
        : "r"(a[0]), "r"(a[1]), "r"(a[2]), "r"(a[3]), "r"(b[0]), "r"(b[1]));
}

__device__ __forceinline__ void cp16(void* dst_smem, const void* src, int bytes) {
    uint32_t d = (uint32_t)__cvta_generic_to_shared(dst_smem);
    asm volatile("cp.async.cg.shared.global [%0], [%1], 16, %2;"
                 :: "r"(d), "l"(src), "r"(bytes));
}

// ---------------- prep: per-edge r, unit vector, padded tf32 cosine basis ----------------
__global__ void prep_kernel(const float* __restrict__ radii) {
    int e = blockIdx.x*blockDim.x + threadIdx.x;
    if (e >= EE) return;
    float x = radii[e*3+0], y = radii[e*3+1], z = radii[e*3+2];
    float r = sqrtf(x*x + y*y + z*z);
    float inv = 1.0f / (r + 1e-8f);
    g_u[e*3+0] = x*inv; g_u[e*3+1] = y*inv; g_u[e*3+2] = z*inv;
    float rs = r * 1.8f;
    #pragma unroll
    for (int b = 0; b < NBP; b++) {
        float v = 0.f;
        if (b < NB) {
            float d = rs - (float)b;
            if (fabsf(d) < 1.0f) {
                float c = cospif(0.5f * d);
                v = f2tf32f(c * c);
            }
        }
        g_basis[e*NBP + b] = v;
    }
}

// ---------------- weight pre-round to tf32 ----------------
__global__ void cvt_kernel(const float* __restrict__ src, float* __restrict__ dst, int n) {
    int i = blockIdx.x*blockDim.x + threadIdx.x;
    if (i < n) dst[i] = f2tf32f(src[i]);
}
// pad w1 [NB,HH] -> [NBP,HH], zero rows NB..NBP-1
__global__ void cvt_pad_kernel(const float* __restrict__ src, float* __restrict__ dst) {
    int i = blockIdx.x*blockDim.x + threadIdx.x;
    if (i >= NBP*HH) return;
    int row = i / HH;
    dst[i] = (row < NB) ? f2tf32f(src[i]) : 0.f;
}

// ---------------- tf32 tensor-core GEMM, cp.async double-buffered ----------------
// C[M,N] = act(A[M,K] @ B[K,N] + bias). BM=128, BN=64, BK=32, 256 thr.
// Requirements: A,B already tf32-rounded; A rows 16B-aligned (K%4==0 or K>=32 and K*4%16==0).
#define AS_STRIDE 36
#define BS_STRIDE 72
#define AS_BUF (128*AS_STRIDE)
#define BS_BUF (32*BS_STRIDE)
#define SMEM_FLOATS (2*AS_BUF + 2*BS_BUF)

template<bool RELU, bool CVTOUT>
__global__ void gemm_tc(const float* __restrict__ A, const float* __restrict__ B,
                        const float* __restrict__ bias, float* __restrict__ C,
                        int M, int N, int K) {
    extern __shared__ float smem[];
    float* As = smem;
    float* Bs = smem + 2*AS_BUF;

    const int tid = threadIdx.x;
    const int lane = tid & 31, wid = tid >> 5;
    const int wm = (wid & 3) * 32;
    const int wn = (wid >> 2) * 32;
    const int m0 = blockIdx.y * 128, n0 = blockIdx.x * 64;
    const int gr = lane >> 2, tg = lane & 3;

    float acc[2][4][4] = {};

    const int ntiles = (K + 31) >> 5;

    auto load_tile = [&](int t, int buf) {
        int kc = t << 5;
        float* Ad = As + buf*AS_BUF;
        #pragma unroll
        for (int j = 0; j < 4; j++) {
            int c = tid + j*256;
            int row = c >> 3, kch = (c & 7) * 4;
            int gk = kc + kch;
            int bytes = (K - gk) * 4;
            bytes = bytes < 0 ? 0 : (bytes > 16 ? 16 : bytes);
            const float* src = bytes ? (A + (size_t)(m0+row)*K + gk) : A;
            cp16(Ad + row*AS_STRIDE + kch, src, bytes);
        }
        float* Bd = Bs + buf*BS_BUF;
        #pragma unroll
        for (int j = 0; j < 2; j++) {
            int c = tid + j*256;
            int k = c >> 4, nch = (c & 15) * 4;
            int gk = kc + k;
            int bytes = 0;
            if (gk < K) {
                bytes = (N - (n0 + nch)) * 4;
                bytes = bytes < 0 ? 0 : (bytes > 16 ? 16 : bytes);
            }
            const float* src = bytes ? (B + (size_t)gk*N + n0 + nch) : B;
            cp16(Bd + k*BS_STRIDE + nch, src, bytes);
        }
        asm volatile("cp.async.commit_group;");
    };

    load_tile(0, 0);

    for (int t = 0; t < ntiles; t++) {
        if (t + 1 < ntiles) {
            load_tile(t + 1, (t + 1) & 1);
            asm volatile("cp.async.wait_group 1;");
        } else {
            asm volatile("cp.async.wait_group 0;");
        }
        __syncthreads();

        const float* Ab = As + (t & 1)*AS_BUF;
        const float* Bb = Bs + (t & 1)*BS_BUF;

        #pragma unroll
        for (int k8 = 0; k8 < 4; k8++) {
            int k0 = k8 * 8;
            uint32_t a[2][4], b[4][2];
            #pragma unroll
            for (int t2 = 0; t2 < 2; t2++) {
                int row = wm + t2*16 + gr;
                a[t2][0] = __float_as_uint(Ab[row*AS_STRIDE     + k0 + tg]);
                a[t2][1] = __float_as_uint(Ab[(row+8)*AS_STRIDE + k0 + tg]);
                a[t2][2] = __float_as_uint(Ab[row*AS_STRIDE     + k0 + 4 + tg]);
                a[t2][3] = __float_as_uint(Ab[(row+8)*AS_STRIDE + k0 + 4 + tg]);
            }
            #pragma unroll
            for (int j = 0; j < 4; j++) {
                int col = wn + j*8 + gr;
                b[j][0] = __float_as_uint(Bb[(k0 + tg)*BS_STRIDE     + col]);
                b[j][1] = __float_as_uint(Bb[(k0 + 4 + tg)*BS_STRIDE + col]);
            }
            #pragma unroll
            for (int t2 = 0; t2 < 2; t2++)
                #pragma unroll
                for (int j = 0; j < 4; j++)
                    mma_tf32(acc[t2][j], a[t2], b[j]);
        }
        __syncthreads();
    }

    #pragma unroll
    for (int t2 = 0; t2 < 2; t2++) {
        #pragma unroll
        for (int j = 0; j < 4; j++) {
            int row = m0 + wm + t2*16 + gr;
            int col = n0 + wn + j*8 + tg*2;
            #pragma unroll
            for (int h = 0; h < 2; h++) {
                int r = row + h*8;
                #pragma unroll
                for (int q = 0; q < 2; q++) {
                    int cn = col + q;
                    if (cn < N) {
                        float v = acc[t2][j][h*2 + q];
                        if (bias) v += bias[cn];
                        if (RELU) v = fmaxf(v, 0.f);
                        if (CVTOUT) v = f2tf32f(v);
                        C[(size_t)r*N + cn] = v;
                    }
                }
            }
        }
    }
}

// ---------------- tensor product + mean-over-K + gated nonlinearity ----------------
template<int LAYER>
__global__ void tp_kernel(const int* __restrict__ nbr, const int* __restrict__ charges) {
    constexpr int M0I = (LAYER==1) ? 1 : 16;
    constexpr int M1I = (LAYER==1) ? 0 : 8;
    constexpr int M0O = (LAYER==3) ? 32 : 16;
    constexpr int NG  = (LAYER==3) ? 0 : 8;
    constexpr int M1O = (LAYER==3) ? 0 : 8;
    constexpr int M0T = M0O + NG;
    constexpr int OFF1 = M0T*M0I;
    constexpr int OFF2 = OFF1 + M0T*M1I;
    constexpr int OFF3 = OFF2 + M1O*M0I;
    constexpr int OFF4 = OFF3 + M1O*M1I;
    constexpr int WTOT = OFF4 + M1O*M1I;

    const float* __restrict__ f0_in = (LAYER==2) ? g_f0a : g_f0b;
    const float* __restrict__ f1_in = (LAYER==2) ? g_f1a : g_f1b;
    float* f0_out = (LAYER==2) ? g_f0b : g_f0a;
    float* f1_out = (LAYER==2) ? g_f1b : g_f1a;

    int n = blockIdx.x;
    int tid = threadIdx.x;

    __shared__ float g0s[16], us[3], g1s[24], ps[8], gates[8];

    float acc = 0.f;

    for (int k = 0; k < KK; k++) {
        int e = n*KK + k;
        int idx = nbr[e];
        if (LAYER == 1) {
            if (tid == 0) g0s[0] = 0.5f * ((float)charges[idx] / 94.0f - 0.5f);
        } else {
            if (tid < M0I) g0s[tid] = 0.5f * f0_in[idx*M0I + tid];
        }
        if (tid >= 32 && tid < 35) us[tid-32] = g_u[e*3 + (tid-32)];
        if (M1I > 0) {
            if (tid >= 36 && tid < 36 + M1I*3) g1s[tid-36] = 0.5f * f1_in[idx*(M1I*3) + (tid-36)];
        }
        __syncthreads();
        if (M1I > 0) {
            if (tid < M1I) ps[tid] = g1s[tid*3]*us[0] + g1s[tid*3+1]*us[1] + g1s[tid*3+2]*us[2];
        }
        __syncthreads();
        const float* __restrict__ We = g_W + (size_t)e * WTOT;
        if (tid < M0T) {
            float s = 0.f;
            #pragma unroll
            for (int i = 0; i < M0I; i++) s += We[tid*M0I + i] * g0s[i];
            if (M1I > 0) {
                #pragma unroll
                for (int i = 0; i < M1I; i++) s += We[OFF1 + tid*M1I + i] * ps[i];
            }
            acc += s;
        } else if (M1O > 0 && tid < M0T + 3*M1O) {
            int q = tid - M0T, o = q/3, c = q - o*3;
            float dot = 0.f;
            #pragma unroll
            for (int i = 0; i < M0I; i++) dot += We[OFF2 + o*M0I + i] * g0s[i];
            float vv = dot * us[c];
            if (M1I > 0) {
                int c1 = (c+1)%3, c2 = (c+2)%3;
                #pragma unroll
                for (int i = 0; i < M1I; i++) vv += We[OFF3 + o*M1I + i] * g1s[i*3 + c];
                #pragma unroll
                for (int i = 0; i < M1I; i++)
                    vv += We[OFF4 + o*M1I + i] * (g1s[i*3+c1]*us[c2] - g1s[i*3+c2]*us[c1]);
            }
            acc += vv;
        }
        __syncthreads();
    }

    float m = acc * (1.0f/16.0f);
    if (tid < M0O) {
        f0_out[n*M0O + tid] = fmaxf(m, 0.f);
    } else if (tid < M0T) {
        gates[tid - M0O] = 1.0f / (1.0f + expf(-m));
    }
    __syncthreads();
    if (M1O > 0 && tid >= M0T && tid < M0T + 3*M1O) {
        int q = tid - M0T, o = q/3, c = q - o*3;
        f1_out[(n*M1O + o)*3 + c] = m * gates[o];
    }
}

// ---------------- final reduce ----------------
__global__ void reduce_kernel(float* __restrict__ out) {
    __shared__ float red[256];
    int j = blockIdx.x;
    float s = 0.f;
    for (int n = threadIdx.x; n < NN; n += 256) s += g_f0a[n*32 + j];
    red[threadIdx.x] = s;
    __syncthreads();
    for (int w = 128; w > 0; w >>= 1) {
        if (threadIdx.x < w) red[threadIdx.x] += red[threadIdx.x + w];
        __syncthreads();
    }
    if (threadIdx.x == 0) out[j] = red[0] * (1.0f/NN);
}

// ---------------- host ----------------
extern "C" void kernel_launch(void* const* d_in, const int* in_sizes, int n_in,
                              void* d_out, int out_size) {
    const float* radii   = (const float*)d_in[0];
    const int*   nbr     = (const int*)d_in[1];
    const int*   charges = (const int*)d_in[2];

    void* p;
    cudaGetSymbolAddress(&p, g_basis); float* basis = (float*)p;
    cudaGetSymbolAddress(&p, g_h1);    float* h1    = (float*)p;
    cudaGetSymbolAddress(&p, g_h2);    float* h2    = (float*)p;
    cudaGetSymbolAddress(&p, g_W);     float* W     = (float*)p;
    cudaGetSymbolAddress(&p, g_w1t);   float* w1t   = (float*)p;
    cudaGetSymbolAddress(&p, g_w2t);   float* w2t   = (float*)p;
    cudaGetSymbolAddress(&p, g_w3t);   float* w3t   = (float*)p;

    const int smem_bytes = SMEM_FLOATS * 4;   // 55296
    cudaFuncSetAttribute(gemm_tc<true , true >, cudaFuncAttributeMaxDynamicSharedMemorySize, smem_bytes);
    cudaFuncSetAttribute(gemm_tc<false, false>, cudaFuncAttributeMaxDynamicSharedMemorySize, smem_bytes);

    prep_kernel<<<(EE+255)/256, 256>>>(radii);

    const int wtot[3] = {32, 832, 768};
    for (int l = 0; l < 3; l++) {
        const float* w1 = (const float*)d_in[3 + 5*l + 0];
        const float* b1 = (const float*)d_in[3 + 5*l + 1];
        const float* w2 = (const float*)d_in[3 + 5*l + 2];
        const float* b2 = (const float*)d_in[3 + 5*l + 3];
        const float* w3 = (const float*)d_in[3 + 5*l + 4];

        cvt_pad_kernel<<<(NBP*HH+255)/256, 256>>>(w1, w1t);
        cvt_kernel<<<(HH*HH+255)/256, 256>>>(w2, w2t, HH*HH);
        cvt_kernel<<<(HH*wtot[l]+255)/256, 256>>>(w3, w3t, HH*wtot[l]);

        dim3 gridH((HH + 63)/64, EE/128);
        gemm_tc<true , true ><<<gridH, 256, smem_bytes>>>(basis, w1t, b1, h1, EE, HH, NBP);
        gemm_tc<true , true ><<<gridH, 256, smem_bytes>>>(h1,    w2t, b2, h2, EE, HH, HH);
        dim3 gridW((wtot[l] + 63)/64, EE/128);
        gemm_tc<false, false><<<gridW, 256, smem_bytes>>>(h2,    w3t, nullptr, W, EE, wtot[l], HH);

        if      (l == 0) tp_kernel<1><<<NN, 64>>>(nbr, charges);
        else if (l == 1) tp_kernel<2><<<NN, 64>>>(nbr, charges);
        else             tp_kernel<3><<<NN, 64>>>(nbr, charges);
    }
    reduce_kernel<<<32, 256>>>((float*)d_out);
}

// round 6
// speedup vs baseline: 2.1873x; 1.0246x over previous
#include <cuda_runtime.h>
#include <math.h>
#include <stdint.h>

#define NN 10000
#define KK 16
#define EE (NN*KK)
#define HH 100
#define NB 10
#define NBP 16   // padded basis width (16B-aligned rows for cp.async)

// ---------------- scratch ----------------
__device__ float g_basis[EE*NBP];
__device__ float g_u[EE*3];
__device__ float g_h1[EE*HH];
__device__ float g_h2[EE*HH];
__device__ float g_W[(size_t)EE*832];
__device__ float g_f0a[NN*32];
__device__ float g_f0b[NN*32];
__device__ float g_f1a[NN*24];
__device__ float g_f1b[NN*24];
__device__ float g_w1t[NBP*HH];
__device__ float g_w2t[HH*HH];
__device__ float g_w3t[HH*832];

// ---------------- helpers ----------------
__device__ __forceinline__ float f2tf32f(float v) {
    uint32_t r;
    asm("cvt.rna.tf32.f32 %0, %1;" : "=r"(r) : "f"(v));
    return __uint_as_float(r);
}

__device__ __forceinline__ void mma_tf32(float* c, const uint32_t* a, const uint32_t* b) {
    asm volatile("mma.sync.aligned.m16n8k8.row.col.f32.tf32.tf32.f32 "
        "{%0,%1,%2,%3}, {%4,%5,%6,%7}, {%8,%9}, {%0,%1,%2,%3};"
        : "+f"(c[0]), "+f"(c[1]), "+f"(c[2]), "+f"(c[3])
        : "r"(a[0]), "r"(a[1]), "r"(a[2]), "r"(a[3]), "r"(b[0]), "r"(b[1]));
}

__device__ __forceinline__ void cp16(void* dst_smem, const void* src, int bytes) {
    uint32_t d = (uint32_t)__cvta_generic_to_shared(dst_smem);
    asm volatile("cp.async.cg.shared.global [%0], [%1], 16, %2;"
                 :: "r"(d), "l"(src), "r"(bytes));
}

// ---------------- prep: per-edge r, unit vector, padded tf32 cosine basis ----------------
__global__ void prep_kernel(const float* __restrict__ radii) {
    int e = blockIdx.x*blockDim.x + threadIdx.x;
    if (e >= EE) return;
    float x = radii[e*3+0], y = radii[e*3+1], z = radii[e*3+2];
    float r = sqrtf(x*x + y*y + z*z);
    float inv = 1.0f / (r + 1e-8f);
    g_u[e*3+0] = x*inv; g_u[e*3+1] = y*inv; g_u[e*3+2] = z*inv;
    float rs = r * 1.8f;
    #pragma unroll
    for (int b = 0; b < NBP; b++) {
        float v = 0.f;
        if (b < NB) {
            float d = rs - (float)b;
            if (fabsf(d) < 1.0f) {
                float c = cospif(0.5f * d);
                v = f2tf32f(c * c);
            }
        }
        g_basis[e*NBP + b] = v;
    }
}

// ---------------- weight pre-round to tf32 ----------------
__global__ void cvt_kernel(const float* __restrict__ src, float* __restrict__ dst, int n) {
    int i = blockIdx.x*blockDim.x + threadIdx.x;
    if (i < n) dst[i] = f2tf32f(src[i]);
}
// pad w1 [NB,HH] -> [NBP,HH], zero rows NB..NBP-1
__global__ void cvt_pad_kernel(const float* __restrict__ src, float* __restrict__ dst) {
    int i = blockIdx.x*blockDim.x + threadIdx.x;
    if (i >= NBP*HH) return;
    int row = i / HH;
    dst[i] = (row < NB) ? f2tf32f(src[i]) : 0.f;
}

// ---------------- tf32 tensor-core GEMM, cp.async double-buffered ----------------
// C[M,N] = act(A[M,K] @ B[K,N] + bias). BM=128, BN=128, BK=32, 256 thr.
// 8 warps in 2(m) x 4(n); warp tile 64x32 = 4x4 m16n8k8 frags.
// A,B already tf32-rounded; A rows 16B-aligned.
#define AS_STRIDE 36
#define BS_STRIDE 136
#define AS_BUF (128*AS_STRIDE)
#define BS_BUF (32*BS_STRIDE)
#define SMEM_FLOATS (2*AS_BUF + 2*BS_BUF)

template<bool RELU, bool CVTOUT>
__global__ void __launch_bounds__(256, 2)
gemm_tc(const float* __restrict__ A, const float* __restrict__ B,
        const float* __restrict__ bias, float* __restrict__ C,
        int M, int N, int K) {
    extern __shared__ float smem[];
    float* As = smem;
    float* Bs = smem + 2*AS_BUF;

    const int tid = threadIdx.x;
    const int lane = tid & 31, wid = tid >> 5;
    const int wm = (wid & 1) * 64;       // 2 m-groups of 64
    const int wn = (wid >> 1) * 32;      // 4 n-groups of 32
    const int m0 = blockIdx.y * 128, n0 = blockIdx.x * 128;
    const int gr = lane >> 2, tg = lane & 3;

    float acc[4][4][4] = {};

    const int ntiles = (K + 31) >> 5;

    auto load_tile = [&](int t, int buf) {
        int kc = t << 5;
        float* Ad = As + buf*AS_BUF;
        #pragma unroll
        for (int j = 0; j < 4; j++) {
            int c = tid + j*256;
            int row = c >> 3, kch = (c & 7) * 4;
            int gk = kc + kch;
            int bytes = (K - gk) * 4;
            bytes = bytes < 0 ? 0 : (bytes > 16 ? 16 : bytes);
            const float* src = bytes ? (A + (size_t)(m0+row)*K + gk) : A;
            cp16(Ad + row*AS_STRIDE + kch, src, bytes);
        }
        float* Bd = Bs + buf*BS_BUF;
        #pragma unroll
        for (int j = 0; j < 4; j++) {
            int c = tid + j*256;
            int k = c >> 5, nch = (c & 31) * 4;
            int gk = kc + k;
            int bytes = 0;
            if (gk < K) {
                bytes = (N - (n0 + nch)) * 4;
                bytes = bytes < 0 ? 0 : (bytes > 16 ? 16 : bytes);
            }
            const float* src = bytes ? (B + (size_t)gk*N + n0 + nch) : B;
            cp16(Bd + k*BS_STRIDE + nch, src, bytes);
        }
        asm volatile("cp.async.commit_group;");
    };

    load_tile(0, 0);

    for (int t = 0; t < ntiles; t++) {
        if (t + 1 < ntiles) {
            load_tile(t + 1, (t + 1) & 1);
            asm volatile("cp.async.wait_group 1;");
        } else {
            asm volatile("cp.async.wait_group 0;");
        }
        __syncthreads();

        const float* Ab = As + (t & 1)*AS_BUF;
        const float* Bb = Bs + (t & 1)*BS_BUF;

        #pragma unroll
        for (int k8 = 0; k8 < 4; k8++) {
            int k0 = k8 * 8;
            uint32_t a[4][4], b[4][2];
            #pragma unroll
            for (int t2 = 0; t2 < 4; t2++) {
                int row = wm + t2*16 + gr;
                a[t2][0] = __float_as_uint(Ab[row*AS_STRIDE     + k0 + tg]);
                a[t2][1] = __float_as_uint(Ab[(row+8)*AS_STRIDE + k0 + tg]);
                a[t2][2] = __float_as_uint(Ab[row*AS_STRIDE     + k0 + 4 + tg]);
                a[t2][3] = __float_as_uint(Ab[(row+8)*AS_STRIDE + k0 + 4 + tg]);
            }
            #pragma unroll
            for (int j = 0; j < 4; j++) {
                int col = wn + j*8 + gr;
                b[j][0] = __float_as_uint(Bb[(k0 + tg)*BS_STRIDE     + col]);
                b[j][1] = __float_as_uint(Bb[(k0 + 4 + tg)*BS_STRIDE + col]);
            }
            #pragma unroll
            for (int t2 = 0; t2 < 4; t2++)
                #pragma unroll
                for (int j = 0; j < 4; j++)
                    mma_tf32(acc[t2][j], a[t2], b[j]);
        }
        __syncthreads();
    }

    #pragma unroll
    for (int t2 = 0; t2 < 4; t2++) {
        #pragma unroll
        for (int j = 0; j < 4; j++) {
            int row = m0 + wm + t2*16 + gr;
            int col = n0 + wn + j*8 + tg*2;
            #pragma unroll
            for (int h = 0; h < 2; h++) {
                int r = row + h*8;
                #pragma unroll
                for (int q = 0; q < 2; q++) {
                    int cn = col + q;
                    if (cn < N) {
                        float v = acc[t2][j][h*2 + q];
                        if (bias) v += bias[cn];
                        if (RELU) v = fmaxf(v, 0.f);
                        if (CVTOUT) v = f2tf32f(v);
                        C[(size_t)r*N + cn] = v;
                    }
                }
            }
        }
    }
}

// ---------------- tensor product + mean-over-K + gated nonlinearity ----------------
template<int LAYER>
__global__ void tp_kernel(const int* __restrict__ nbr, const int* __restrict__ charges) {
    constexpr int M0I = (LAYER==1) ? 1 : 16;
    constexpr int M1I = (LAYER==1) ? 0 : 8;
    constexpr int M0O = (LAYER==3) ? 32 : 16;
    constexpr int NG  = (LAYER==3) ? 0 : 8;
    constexpr int M1O = (LAYER==3) ? 0 : 8;
    constexpr int M0T = M0O + NG;
    constexpr int OFF1 = M0T*M0I;
    constexpr int OFF2 = OFF1 + M0T*M1I;
    constexpr int OFF3 = OFF2 + M1O*M0I;
    constexpr int OFF4 = OFF3 + M1O*M1I;
    constexpr int WTOT = OFF4 + M1O*M1I;

    const float* __restrict__ f0_in = (LAYER==2) ? g_f0a : g_f0b;
    const float* __restrict__ f1_in = (LAYER==2) ? g_f1a : g_f1b;
    float* f0_out = (LAYER==2) ? g_f0b : g_f0a;
    float* f1_out = (LAYER==2) ? g_f1b : g_f1a;

    int n = blockIdx.x;
    int tid = threadIdx.x;

    __shared__ float g0s[16], us[3], g1s[24], ps[8], gates[8];

    float acc = 0.f;

    for (int k = 0; k < KK; k++) {
        int e = n*KK + k;
        int idx = nbr[e];
        if (LAYER == 1) {
            if (tid == 0) g0s[0] = 0.5f * ((float)charges[idx] / 94.0f - 0.5f);
        } else {
            if (tid < M0I) g0s[tid] = 0.5f * f0_in[idx*M0I + tid];
        }
        if (tid >= 32 && tid < 35) us[tid-32] = g_u[e*3 + (tid-32)];
        if (M1I > 0) {
            if (tid >= 36 && tid < 36 + M1I*3) g1s[tid-36] = 0.5f * f1_in[idx*(M1I*3) + (tid-36)];
        }
        __syncthreads();
        if (M1I > 0) {
            if (tid < M1I) ps[tid] = g1s[tid*3]*us[0] + g1s[tid*3+1]*us[1] + g1s[tid*3+2]*us[2];
        }
        __syncthreads();
        const float* __restrict__ We = g_W + (size_t)e * WTOT;
        if (tid < M0T) {
            float s = 0.f;
            #pragma unroll
            for (int i = 0; i < M0I; i++) s += We[tid*M0I + i] * g0s[i];
            if (M1I > 0) {
                #pragma unroll
                for (int i = 0; i < M1I; i++) s += We[OFF1 + tid*M1I + i] * ps[i];
            }
            acc += s;
        } else if (M1O > 0 && tid < M0T + 3*M1O) {
            int q = tid - M0T, o = q/3, c = q - o*3;
            float dot = 0.f;
            #pragma unroll
            for (int i = 0; i < M0I; i++) dot += We[OFF2 + o*M0I + i] * g0s[i];
            float vv = dot * us[c];
            if (M1I > 0) {
                int c1 = (c+1)%3, c2 = (c+2)%3;
                #pragma unroll
                for (int i = 0; i < M1I; i++) vv += We[OFF3 + o*M1I + i] * g1s[i*3 + c];
                #pragma unroll
                for (int i = 0; i < M1I; i++)
                    vv += We[OFF4 + o*M1I + i] * (g1s[i*3+c1]*us[c2] - g1s[i*3+c2]*us[c1]);
            }
            acc += vv;
        }
        __syncthreads();
    }

    float m = acc * (1.0f/16.0f);
    if (tid < M0O) {
        f0_out[n*M0O + tid] = fmaxf(m, 0.f);
    } else if (tid < M0T) {
        gates[tid - M0O] = 1.0f / (1.0f + expf(-m));
    }
    __syncthreads();
    if (M1O > 0 && tid >= M0T && tid < M0T + 3*M1O) {
        int q = tid - M0T, o = q/3, c = q - o*3;
        f1_out[(n*M1O + o)*3 + c] = m * gates[o];
    }
}

// ---------------- final reduce ----------------
__global__ void reduce_kernel(float* __restrict__ out) {
    __shared__ float red[256];
    int j = blockIdx.x;
    float s = 0.f;
    for (int n = threadIdx.x; n < NN; n += 256) s += g_f0a[n*32 + j];
    red[threadIdx.x] = s;
    __syncthreads();
    for (int w = 128; w > 0; w >>= 1) {
        if (threadIdx.x < w) red[threadIdx.x] += red[threadIdx.x + w];
        __syncthreads();
    }
    if (threadIdx.x == 0) out[j] = red[0] * (1.0f/NN);
}

// ---------------- host ----------------
extern "C" void kernel_launch(void* const* d_in, const int* in_sizes, int n_in,
                              void* d_out, int out_size) {
    const float* radii   = (const float*)d_in[0];
    const int*   nbr     = (const int*)d_in[1];
    const int*   charges = (const int*)d_in[2];

    void* p;
    cudaGetSymbolAddress(&p, g_basis); float* basis = (float*)p;
    cudaGetSymbolAddress(&p, g_h1);    float* h1    = (float*)p;
    cudaGetSymbolAddress(&p, g_h2);    float* h2    = (float*)p;
    cudaGetSymbolAddress(&p, g_W);     float* W     = (float*)p;
    cudaGetSymbolAddress(&p, g_w1t);   float* w1t   = (float*)p;
    cudaGetSymbolAddress(&p, g_w2t);   float* w2t   = (float*)p;
    cudaGetSymbolAddress(&p, g_w3t);   float* w3t   = (float*)p;

    const int smem_bytes = SMEM_FLOATS * 4;   // 71680
    cudaFuncSetAttribute(gemm_tc<true , true >, cudaFuncAttributeMaxDynamicSharedMemorySize, smem_bytes);
    cudaFuncSetAttribute(gemm_tc<false, false>, cudaFuncAttributeMaxDynamicSharedMemorySize, smem_bytes);

    prep_kernel<<<(EE+255)/256, 256>>>(radii);

    const int wtot[3] = {32, 832, 768};
    for (int l = 0; l < 3; l++) {
        const float* w1 = (const float*)d_in[3 + 5*l + 0];
        const float* b1 = (const float*)d_in[3 + 5*l + 1];
        const float* w2 = (const float*)d_in[3 + 5*l + 2];
        const float* b2 = (const float*)d_in[3 + 5*l + 3];
        const float* w3 = (const float*)d_in[3 + 5*l + 4];

        cvt_pad_kernel<<<(NBP*HH+255)/256, 256>>>(w1, w1t);
        cvt_kernel<<<(HH*HH+255)/256, 256>>>(w2, w2t, HH*HH);
        cvt_kernel<<<(HH*wtot[l]+255)/256, 256>>>(w3, w3t, HH*wtot[l]);

        dim3 gridH(1, EE/128);                     // N=100 fits one 128-col tile
        gemm_tc<true , true ><<<gridH, 256, smem_bytes>>>(basis, w1t, b1, h1, EE, HH, NBP);
        gemm_tc<true , true ><<<gridH, 256, smem_bytes>>>(h1,    w2t, b2, h2, EE, HH, HH);
        dim3 gridW((wtot[l] + 127)/128, EE/128);
        gemm_tc<false, false><<<gridW, 256, smem_bytes>>>(h2,    w3t, nullptr, W, EE, wtot[l], HH);

        if      (l == 0) tp_kernel<1><<<NN, 64>>>(nbr, charges);
        else if (l == 1) tp_kernel<2><<<NN, 64>>>(nbr, charges);
        else             tp_kernel<3><<<NN, 64>>>(nbr, charges);
    }
    reduce_kernel<<<32, 256>>>((float*)d_out);
}